// round 5
// baseline (speedup 1.0000x reference)
#include <cuda_runtime.h>
#include <math.h>

// Problem constants (shapes fixed by the reference)
#define NMAX 100000
#define EMAX 1600000

#define NEG_INF __int_as_float(0xff800000)

// ---- scratch (device globals: allocation-free rule) ----
__device__ float  g_xl[(size_t)NMAX * 128];  // source transform, current layer
__device__ float  g_xr[(size_t)NMAX * 128];  // target transform, current layer
__device__ float  g_h [(size_t)NMAX * 64];   // node features between layers
__device__ int    g_deg[NMAX];               // degree, then scatter cursor
__device__ int    g_rowptr[NMAX + 1];
__device__ int4   g_epack[EMAX];             // (edge id, src, dst, -) CSR-by-dst order
__device__ float2 g_logit[EMAX];             // per-edge logits -> unnormalized alphas
__device__ float2 g_inv[NMAX];               // per-node 1/denom per head

// ---------------- CSR build ----------------

__global__ void zero_kernel(int n) {
    int i = blockIdx.x * blockDim.x + threadIdx.x;
    if (i < n) g_deg[i] = 0;
}

__global__ void hist_kernel(const int* __restrict__ dst, int ne) {
    int i = blockIdx.x * blockDim.x + threadIdx.x;
    if (i < ne) atomicAdd(&g_deg[dst[i]], 1);
}

// single-block exclusive scan over g_deg -> g_rowptr; resets g_deg to 0 (cursor)
__global__ void scan_kernel(int n, int ne) {
    __shared__ int ss[1024];
    int t = threadIdx.x;
    int per = (n + 1023) >> 10;
    int lo = t * per;
    int hi = lo + per; if (hi > n) hi = n;
    int s = 0;
    for (int i = lo; i < hi; i++) s += g_deg[i];
    ss[t] = s;
    __syncthreads();
    for (int off = 1; off < 1024; off <<= 1) {
        int v = (t >= off) ? ss[t - off] : 0;
        __syncthreads();
        ss[t] += v;
        __syncthreads();
    }
    int run = (t == 0) ? 0 : ss[t - 1];
    for (int i = lo; i < hi; i++) {
        run += g_deg[i];
        g_rowptr[i] = run - g_deg[i];
        g_deg[i] = 0;                       // becomes scatter cursor
    }
    if (t == 0) g_rowptr[n] = ne;
}

__global__ void scatter_kernel(const int* __restrict__ src,
                               const int* __restrict__ dst, int ne) {
    int i = blockIdx.x * blockDim.x + threadIdx.x;
    if (i < ne) {
        int d = dst[i];
        int pos = g_rowptr[d] + atomicAdd(&g_deg[d], 1);
        g_epack[pos] = make_int4(i, src[i], d, 0);
    }
}

// ---------------- node GEMM: out = act(in) @ W + b ----------------

template <int K>
__device__ __forceinline__ void ldvec(const float* p, float* v) {
    if constexpr (K == 4) {
        float4 t = __ldg((const float4*)p);
        v[0] = t.x; v[1] = t.y; v[2] = t.z; v[3] = t.w;
    } else {
        float2 t = __ldg((const float2*)p);
        v[0] = t.x; v[1] = t.y;
    }
}

template <int NC>
__global__ void __launch_bounds__(256)
gemm_kernel(const float* __restrict__ ext, int insel, int fin,
            const float* __restrict__ W, const float* __restrict__ bias,
            int outsel, int n) {
    const float* in = insel ? g_h : ext;
    float* out = outsel ? g_xr : g_xl;
    const int wout = 32 * NC;
    __shared__ float xs[64][81];
    int n0 = blockIdx.x * 64;

    for (int idx = threadIdx.x; idx < 64 * fin; idx += 256) {
        int nl = idx / fin, f = idx - nl * fin;
        float v = 0.f;
        int nd = n0 + nl;
        if (nd < n) v = in[(size_t)nd * fin + f];
        if (insel) v = (v > 0.f) ? v : 0.01f * v;   // inter-layer leaky_relu(0.01)
        xs[nl][f] = v;
    }
    __syncthreads();

    int r = threadIdx.x >> 5, c = threadIdx.x & 31;
    float acc[8][NC];
#pragma unroll
    for (int j = 0; j < 8; j++)
#pragma unroll
        for (int k = 0; k < NC; k++) acc[j][k] = 0.f;

    for (int f = 0; f < fin; f++) {
        float wv[NC];
        ldvec<NC>(W + (size_t)f * wout + c * NC, wv);
#pragma unroll
        for (int j = 0; j < 8; j++) {
            float a = xs[r * 8 + j][f];
#pragma unroll
            for (int k = 0; k < NC; k++) acc[j][k] = fmaf(a, wv[k], acc[j][k]);
        }
    }
#pragma unroll
    for (int j = 0; j < 8; j++) {
        int nd = n0 + r * 8 + j;
        if (nd < n) {
#pragma unroll
            for (int k = 0; k < NC; k++)
                out[(size_t)nd * wout + c * NC + k] = acc[j][k] + __ldg(&bias[c * NC + k]);
        }
    }
}

// ---------------- phase 1: edge-parallel GATv2 logits ----------------
// warp per edge (grid-stride). Iterations fully independent -> SHFL/MUFU chains
// from different edges pipeline. Lanes split channels (K per lane; 0-15 head0).

template <int K>
__global__ void __launch_bounds__(256)
logit_kernel(const float* __restrict__ edge_attr,
             const float* __restrict__ We,
             const float* __restrict__ att, int ne) {
    constexpr int WD = 32 * K;
    const unsigned FULL = 0xffffffffu;
    int lane = threadIdx.x & 31;
    int gw = (blockIdx.x * blockDim.x + threadIdx.x) >> 5;
    int nw = (gridDim.x * blockDim.x) >> 5;

    float wreg[10][K];
#pragma unroll
    for (int f = 0; f < 10; f++)
#pragma unroll
        for (int k = 0; k < K; k++)
            wreg[f][k] = __ldg(&We[f * WD + lane * K + k]);
    float areg[K];
#pragma unroll
    for (int k = 0; k < K; k++) areg[k] = __ldg(&att[lane * K + k]);

    for (int pos = gw; pos < ne; pos += nw) {
        int4 es = __ldg(&g_epack[pos]);               // (eid, src, dst, -)
        const float2* ea2 = (const float2*)(edge_attr + (size_t)es.x * 10);
        float ev[10];
#pragma unroll
        for (int f2 = 0; f2 < 5; f2++) {
            float2 t = __ldg(&ea2[f2]);
            ev[f2 * 2] = t.x; ev[f2 * 2 + 1] = t.y;
        }
        float xv[K], rv[K];
        ldvec<K>(g_xl + (size_t)es.y * WD + lane * K, xv);
        ldvec<K>(g_xr + (size_t)es.z * WD + lane * K, rv);

        float ef[K];
#pragma unroll
        for (int k = 0; k < K; k++) ef[k] = 0.f;
#pragma unroll
        for (int f = 0; f < 10; f++)
#pragma unroll
            for (int k = 0; k < K; k++) ef[k] = fmaf(ev[f], wreg[f][k], ef[k]);

        float p = 0.f;
#pragma unroll
        for (int k = 0; k < K; k++) {
            float m = xv[k] + rv[k] + ef[k];
            m = fmaxf(m, 0.f) + 0.2f * fminf(m, 0.f);  // leaky_relu(0.2)
            p = fmaf(m, areg[k], p);
        }
        // per-head reduce over the two 16-lane halves
        p += __shfl_xor_sync(FULL, p, 1, 16);
        p += __shfl_xor_sync(FULL, p, 2, 16);
        p += __shfl_xor_sync(FULL, p, 4, 16);
        p += __shfl_xor_sync(FULL, p, 8, 16);
        float l1 = __shfl_sync(FULL, p, 16);
        if (lane == 0) g_logit[pos] = make_float2(p, l1);
    }
}

// ---------------- phase 2: per-node softmax over contiguous CSR range ----------------
// thread per node; overwrites g_logit with unnormalized ex, stores 1/denom.

__global__ void softmax_kernel(int n) {
    int i = blockIdx.x * blockDim.x + threadIdx.x;
    if (i >= n) return;
    int s0 = g_rowptr[i], s1 = g_rowptr[i + 1];
    float m0 = NEG_INF, m1 = NEG_INF;
    for (int p = s0; p < s1; p++) {
        float2 l = g_logit[p];
        m0 = fmaxf(m0, l.x);
        m1 = fmaxf(m1, l.y);
    }
    float d0 = 0.f, d1 = 0.f;
    for (int p = s0; p < s1; p++) {
        float2 l = g_logit[p];
        float e0 = __expf(l.x - m0);
        float e1 = __expf(l.y - m1);
        d0 += e0; d1 += e1;
        g_logit[p] = make_float2(e0, e1);
    }
    g_inv[i] = make_float2(1.f / fmaxf(d0, 1e-16f), 1.f / fmaxf(d1, 1e-16f));
}

// ---------------- phase 3: node-parallel weighted aggregation ----------------
// warp per node, lanes split channels. Per edge: broadcast alpha + one gather + FMA.
// No shuffles, no exp, no loop-carried rescale -> fully pipelined.

template <int K, bool CONCAT>
__global__ void __launch_bounds__(256)
aggregate_kernel(const float* __restrict__ bias,
                 float* __restrict__ extout, int out_ext, int n) {
    constexpr int WD = 32 * K;
    const unsigned FULL = 0xffffffffu;
    int lane = threadIdx.x & 31;
    int warp = threadIdx.x >> 5;
    bool head1 = (lane >= 16);
    float* outp = out_ext ? extout : g_h;

    for (int node = blockIdx.x * 8 + warp; node < n; node += gridDim.x * 8) {
        int s0 = g_rowptr[node], s1 = g_rowptr[node + 1];
        float acc[K];
#pragma unroll
        for (int k = 0; k < K; k++) acc[k] = 0.f;

#pragma unroll 4
        for (int p = s0; p < s1; p++) {
            float2 ex = __ldg(&g_logit[p]);           // broadcast
            int src = __ldg(&g_epack[p].y);           // broadcast
            float w = head1 ? ex.y : ex.x;
            float xv[K];
            ldvec<K>(g_xl + (size_t)src * WD + lane * K, xv);
#pragma unroll
            for (int k = 0; k < K; k++) acc[k] = fmaf(w, xv[k], acc[k]);
        }

        float2 iv = __ldg(&g_inv[node]);
        float inv = head1 ? iv.y : iv.x;
        if constexpr (CONCAT) {
#pragma unroll
            for (int k = 0; k < K; k++)
                outp[(size_t)node * WD + lane * K + k] =
                    acc[k] * inv + __ldg(&bias[lane * K + k]);
        } else {
            float o[K];
#pragma unroll
            for (int k = 0; k < K; k++) {
                o[k] = acc[k] * inv;
                o[k] = 0.5f * (o[k] + __shfl_xor_sync(FULL, o[k], 16));  // head mean
            }
            if (lane < 16) {
#pragma unroll
                for (int k = 0; k < K; k++)
                    outp[(size_t)node * (WD / 2) + lane * K + k] =
                        o[k] + __ldg(&bias[lane * K + k]);
            }
        }
    }
}

// ---------------- launch ----------------

extern "C" void kernel_launch(void* const* d_in, const int* in_sizes, int n_in,
                              void* d_out, int out_size) {
    const float* x     = (const float*)d_in[0];
    const int*   ei    = (const int*)  d_in[1];
    const float* ea    = (const float*)d_in[2];
    const float* Wl0   = (const float*)d_in[3];
    const float* bl0   = (const float*)d_in[4];
    const float* Wr0   = (const float*)d_in[5];
    const float* br0   = (const float*)d_in[6];
    const float* We0   = (const float*)d_in[7];
    const float* att0  = (const float*)d_in[8];
    const float* bias0 = (const float*)d_in[9];
    const float* Wl1   = (const float*)d_in[10];
    const float* bl1   = (const float*)d_in[11];
    const float* Wr1   = (const float*)d_in[12];
    const float* br1   = (const float*)d_in[13];
    const float* We1   = (const float*)d_in[14];
    const float* att1  = (const float*)d_in[15];
    const float* bias1 = (const float*)d_in[16];
    float* out = (float*)d_out;

    int n  = in_sizes[0] / 79;    // nodes
    int ne = in_sizes[1] / 2;     // edges
    const int* srcp = ei;
    const int* dstp = ei + ne;

    // CSR by destination (rebuilt every call; no caching)
    zero_kernel   <<<(n  + 255) / 256, 256>>>(n);
    hist_kernel   <<<(ne + 255) / 256, 256>>>(dstp, ne);
    scan_kernel   <<<1, 1024>>>(n, ne);
    scatter_kernel<<<(ne + 255) / 256, 256>>>(srcp, dstp, ne);

    int gb = (n + 63) / 64;
    int nb = (n + 255) / 256;

    // layer 0: 79 -> 2x32 concat (width 64)
    gemm_kernel<2><<<gb, 256>>>(x, 0, 79, Wl0, bl0, 0, n);
    gemm_kernel<2><<<gb, 256>>>(x, 0, 79, Wr0, br0, 1, n);
    logit_kernel<2><<<4096, 256>>>(ea, We0, att0, ne);
    softmax_kernel<<<nb, 256>>>(n);
    aggregate_kernel<2, true><<<4096, 256>>>(bias0, out, 0, n);

    // layers 1,2: 64 -> 2x64 mean (width 64), leaky_relu(0.01) on input inside gemm
    for (int i = 0; i < 2; i++) {
        gemm_kernel<4><<<gb, 256>>>(nullptr, 1, 64, Wl1 + (size_t)i * 64 * 128,
                                    bl1 + i * 128, 0, n);
        gemm_kernel<4><<<gb, 256>>>(nullptr, 1, 64, Wr1 + (size_t)i * 64 * 128,
                                    br1 + i * 128, 1, n);
        logit_kernel<4><<<4096, 256>>>(ea, We1 + (size_t)i * 10 * 128,
                                       att1 + i * 2 * 64, ne);
        softmax_kernel<<<nb, 256>>>(n);
        aggregate_kernel<4, false><<<4096, 256>>>(bias1 + i * 64, out,
                                                  (i == 1) ? 1 : 0, n);
    }
}

// round 6
// speedup vs baseline: 1.2655x; 1.2655x over previous
#include <cuda_runtime.h>
#include <math.h>

// Problem constants (shapes fixed by the reference)
#define NMAX 100000
#define EMAX 1600000

#define NEG_INF __int_as_float(0xff800000)

// ---- scratch (device globals: allocation-free rule) ----
__device__ float g_xl[(size_t)NMAX * 128];   // source transform, current layer
__device__ float g_xr[(size_t)NMAX * 128];   // target transform, current layer
__device__ float g_h [(size_t)NMAX * 64];    // node features between layers
__device__ int   g_deg[NMAX];                // degree (recomputed every call)
__device__ int   g_cur[NMAX];                // persistent mod-cursor (zero-init .bss)
__device__ int   g_rowptr[NMAX + 1];
__device__ int2  g_epack[EMAX];              // (edge id, src node) in CSR-by-dst order

// ---------------- CSR build ----------------

__global__ void hist_kernel(const int* __restrict__ dst, int ne) {
    int i = blockIdx.x * blockDim.x + threadIdx.x;
    if (i < ne) atomicAdd(&g_deg[dst[i]], 1);
}

// single-block exclusive scan over g_deg -> g_rowptr; re-zeroes g_deg for next call
__global__ void scan_kernel(int n, int ne) {
    __shared__ int ss[1024];
    int t = threadIdx.x;
    int per = (n + 1023) >> 10;
    int lo = t * per;
    int hi = lo + per; if (hi > n) hi = n;
    int s = 0;
    for (int i = lo; i < hi; i++) s += g_deg[i];
    ss[t] = s;
    __syncthreads();
    for (int off = 1; off < 1024; off <<= 1) {
        int v = (t >= off) ? ss[t - off] : 0;
        __syncthreads();
        ss[t] += v;
        __syncthreads();
    }
    int run = (t == 0) ? 0 : ss[t - 1];
    for (int i = lo; i < hi; i++) {
        run += g_deg[i];
        g_rowptr[i] = run - g_deg[i];
        g_deg[i] = 0;                       // restore invariant: g_deg zeroed for next call
    }
    if (t == 0) g_rowptr[n] = ne;
}

// persistent cursor: every call adds exactly deg[d] to g_cur[d], so the residues
// mod deg are a permutation of 0..deg-1 on every call (deg>=1 whenever touched).
__global__ void scatter_kernel(const int* __restrict__ src,
                               const int* __restrict__ dst, int ne) {
    int i = blockIdx.x * blockDim.x + threadIdx.x;
    if (i < ne) {
        int d = dst[i];
        int r0 = g_rowptr[d], deg = g_rowptr[d + 1] - r0;
        int slot = atomicAdd(&g_cur[d], 1) % deg;
        g_epack[r0 + slot] = make_int2(i, src[i]);
    }
}

// ---------------- node GEMM: out = act(in) @ W + b ----------------

template <int K>
__device__ __forceinline__ void ldvec(const float* p, float* v) {
    if constexpr (K == 4) {
        float4 t = __ldg((const float4*)p);
        v[0] = t.x; v[1] = t.y; v[2] = t.z; v[3] = t.w;
    } else {
        float2 t = __ldg((const float2*)p);
        v[0] = t.x; v[1] = t.y;
    }
}

template <int NC>
__global__ void __launch_bounds__(256)
gemm_kernel(const float* __restrict__ ext, int insel, int fin,
            const float* __restrict__ W, const float* __restrict__ bias,
            int outsel, int n) {
    const float* in = insel ? g_h : ext;
    float* out = outsel ? g_xr : g_xl;
    const int wout = 32 * NC;
    __shared__ float xs[64][81];
    int n0 = blockIdx.x * 64;

    for (int idx = threadIdx.x; idx < 64 * fin; idx += 256) {
        int nl = idx / fin, f = idx - nl * fin;
        float v = 0.f;
        int nd = n0 + nl;
        if (nd < n) v = in[(size_t)nd * fin + f];
        if (insel) v = (v > 0.f) ? v : 0.01f * v;   // inter-layer leaky_relu(0.01)
        xs[nl][f] = v;
    }
    __syncthreads();

    int r = threadIdx.x >> 5, c = threadIdx.x & 31;
    float acc[8][NC];
#pragma unroll
    for (int j = 0; j < 8; j++)
#pragma unroll
        for (int k = 0; k < NC; k++) acc[j][k] = 0.f;

    for (int f = 0; f < fin; f++) {
        float wv[NC];
        ldvec<NC>(W + (size_t)f * wout + c * NC, wv);
#pragma unroll
        for (int j = 0; j < 8; j++) {
            float a = xs[r * 8 + j][f];
#pragma unroll
            for (int k = 0; k < NC; k++) acc[j][k] = fmaf(a, wv[k], acc[j][k]);
        }
    }
#pragma unroll
    for (int j = 0; j < 8; j++) {
        int nd = n0 + r * 8 + j;
        if (nd < n) {
#pragma unroll
            for (int k = 0; k < NC; k++)
                out[(size_t)nd * wout + c * NC + k] = acc[j][k] + __ldg(&bias[c * NC + k]);
        }
    }
}

// ---------------- fused GATv2 edge+softmax+aggregate (node-centric) ----------------
// warp per node; lanes split channels (K per lane, lanes 0-15 = head0, 16-31 = head1).
// Edges processed in PAIRS: two independent logit computations (overlapping SHFL/MUFU
// chains, 2x MLP), then ONE combined online-softmax update -> half the loop-carried
// serial chain iterations.

template <int K>
__device__ __forceinline__ float edge_logit(
    const float* __restrict__ edge_attr, int2 es, int lane,
    const float (&wreg)[10][K], const float (&areg)[K], const float (&xrv)[K],
    float (&xv)[K]) {
    constexpr int WD = 32 * K;
    const unsigned FULL = 0xffffffffu;
    const float2* ea2 = (const float2*)(edge_attr + (size_t)es.x * 10);
    float ef[K];
#pragma unroll
    for (int k = 0; k < K; k++) ef[k] = 0.f;
#pragma unroll
    for (int f2 = 0; f2 < 5; f2++) {
        float2 t = __ldg(&ea2[f2]);
#pragma unroll
        for (int k = 0; k < K; k++) {
            ef[k] = fmaf(t.x, wreg[f2 * 2][k], ef[k]);
            ef[k] = fmaf(t.y, wreg[f2 * 2 + 1][k], ef[k]);
        }
    }
    ldvec<K>(g_xl + (size_t)es.y * WD + lane * K, xv);
    float p = 0.f;
#pragma unroll
    for (int k = 0; k < K; k++) {
        float m = xv[k] + xrv[k] + ef[k];
        m = fmaxf(m, 0.f) + 0.2f * fminf(m, 0.f);      // leaky_relu(0.2)
        p = fmaf(m, areg[k], p);
    }
    // per-head reduce: every lane ends with its own head's logit
    p += __shfl_xor_sync(FULL, p, 1, 16);
    p += __shfl_xor_sync(FULL, p, 2, 16);
    p += __shfl_xor_sync(FULL, p, 4, 16);
    p += __shfl_xor_sync(FULL, p, 8, 16);
    return p;
}

template <int K, bool CONCAT>
__global__ void __launch_bounds__(256)
agg_kernel(const float* __restrict__ edge_attr,
           const float* __restrict__ We,
           const float* __restrict__ att,
           const float* __restrict__ bias,
           float* __restrict__ extout, int out_ext, int n) {
    constexpr int WD = 32 * K;
    const unsigned FULL = 0xffffffffu;
    int lane = threadIdx.x & 31;
    int warp = threadIdx.x >> 5;

    float wreg[10][K];
#pragma unroll
    for (int f = 0; f < 10; f++)
#pragma unroll
        for (int k = 0; k < K; k++)
            wreg[f][k] = __ldg(&We[f * WD + lane * K + k]);
    float areg[K];
#pragma unroll
    for (int k = 0; k < K; k++) areg[k] = __ldg(&att[lane * K + k]);

    float* outp = out_ext ? extout : g_h;

    for (int node = blockIdx.x * 8 + warp; node < n; node += gridDim.x * 8) {
        int s0 = g_rowptr[node], s1 = g_rowptr[node + 1];
        float xrv[K];
        ldvec<K>(g_xr + (size_t)node * WD + lane * K, xrv);

        float acc[K];
#pragma unroll
        for (int k = 0; k < K; k++) acc[k] = 0.f;
        float mh = NEG_INF;
        float ssum = 0.f;

        int p0 = s0;
        for (; p0 + 2 <= s1; p0 += 2) {
            int2 esa = __ldg(&g_epack[p0]);
            int2 esb = __ldg(&g_epack[p0 + 1]);
            float xva[K], xvb[K];
            float pa = edge_logit<K>(edge_attr, esa, lane, wreg, areg, xrv, xva);
            float pb = edge_logit<K>(edge_attr, esb, lane, wreg, areg, xrv, xvb);

            float mnew = fmaxf(mh, fmaxf(pa, pb));
            float sc = __expf(mh - mnew);      // 0 when mh = -inf
            float wa = __expf(pa - mnew);
            float wb = __expf(pb - mnew);
            ssum = fmaf(ssum, sc, wa + wb);
#pragma unroll
            for (int k = 0; k < K; k++)
                acc[k] = fmaf(acc[k], sc, fmaf(wa, xva[k], wb * xvb[k]));
            mh = mnew;
        }
        for (; p0 < s1; p0++) {
            int2 es = __ldg(&g_epack[p0]);
            float xv[K];
            float p = edge_logit<K>(edge_attr, es, lane, wreg, areg, xrv, xv);
            float mnew = fmaxf(mh, p);
            float sc = __expf(mh - mnew);
            float w  = __expf(p - mnew);
            ssum = fmaf(ssum, sc, w);
#pragma unroll
            for (int k = 0; k < K; k++) acc[k] = fmaf(acc[k], sc, w * xv[k]);
            mh = mnew;
        }

        float inv = 1.f / fmaxf(ssum, 1e-16f);
        if constexpr (CONCAT) {
#pragma unroll
            for (int k = 0; k < K; k++)
                outp[(size_t)node * WD + lane * K + k] =
                    acc[k] * inv + __ldg(&bias[lane * K + k]);
        } else {
            float o[K];
#pragma unroll
            for (int k = 0; k < K; k++) {
                o[k] = acc[k] * inv;
                o[k] = 0.5f * (o[k] + __shfl_xor_sync(FULL, o[k], 16));  // head mean
            }
            if (lane < 16) {
#pragma unroll
                for (int k = 0; k < K; k++)
                    outp[(size_t)node * (WD / 2) + lane * K + k] =
                        o[k] + __ldg(&bias[lane * K + k]);
            }
        }
    }
}

// ---------------- launch ----------------

extern "C" void kernel_launch(void* const* d_in, const int* in_sizes, int n_in,
                              void* d_out, int out_size) {
    const float* x     = (const float*)d_in[0];
    const int*   ei    = (const int*)  d_in[1];
    const float* ea    = (const float*)d_in[2];
    const float* Wl0   = (const float*)d_in[3];
    const float* bl0   = (const float*)d_in[4];
    const float* Wr0   = (const float*)d_in[5];
    const float* br0   = (const float*)d_in[6];
    const float* We0   = (const float*)d_in[7];
    const float* att0  = (const float*)d_in[8];
    const float* bias0 = (const float*)d_in[9];
    const float* Wl1   = (const float*)d_in[10];
    const float* bl1   = (const float*)d_in[11];
    const float* Wr1   = (const float*)d_in[12];
    const float* br1   = (const float*)d_in[13];
    const float* We1   = (const float*)d_in[14];
    const float* att1  = (const float*)d_in[15];
    const float* bias1 = (const float*)d_in[16];
    float* out = (float*)d_out;

    int n  = in_sizes[0] / 79;    // nodes
    int ne = in_sizes[1] / 2;     // edges
    const int* srcp = ei;
    const int* dstp = ei + ne;

    // CSR by destination. g_deg is zeroed (zero-init .bss at load; scan re-zeroes
    // after every call). g_cur is a persistent mod-cursor.
    hist_kernel   <<<(ne + 255) / 256, 256>>>(dstp, ne);
    scan_kernel   <<<1, 1024>>>(n, ne);
    scatter_kernel<<<(ne + 255) / 256, 256>>>(srcp, dstp, ne);

    int gb = (n + 63) / 64;

    // layer 0: 79 -> 2x32 concat (width 64)
    gemm_kernel<2><<<gb, 256>>>(x, 0, 79, Wl0, bl0, 0, n);   // 4th launch -> ncu window
    gemm_kernel<2><<<gb, 256>>>(x, 0, 79, Wr0, br0, 1, n);
    agg_kernel<2, true><<<4096, 256>>>(ea, We0, att0, bias0, out, 0, n);

    // layers 1,2: 64 -> 2x64 mean (width 64), leaky_relu(0.01) on input inside gemm
    for (int i = 0; i < 2; i++) {
        gemm_kernel<4><<<gb, 256>>>(nullptr, 1, 64, Wl1 + (size_t)i * 64 * 128,
                                    bl1 + i * 128, 0, n);
        gemm_kernel<4><<<gb, 256>>>(nullptr, 1, 64, Wr1 + (size_t)i * 64 * 128,
                                    br1 + i * 128, 1, n);
        agg_kernel<4, false><<<4096, 256>>>(ea, We1 + (size_t)i * 10 * 128,
                                            att1 + i * 2 * 64, bias1 + i * 64,
                                            out, (i == 1) ? 1 : 0, n);
    }
}